// round 3
// baseline (speedup 1.0000x reference)
#include <cuda_runtime.h>

// Problem constants: B=4, C=64, N=512, H=128, 2C=128.
#define B_ 4
#define C_ 64
#define N_ 512
#define H_ 128

typedef unsigned long long u64;

// Scratch:
//  g_Adup[b][h][n] = dup(b1[h] + sum_c x[b,c,n]*W1[c][h])       (each as (a,a) u64)
//  g_Bv  [b][h][n] =            sum_c x[b,c,n]*W1[C+c][h]
//  g_P[b][n] = b2 + sum_h (w_h/2)*A,   g_Q[b][n] = sum_h (w_h/2)*Bv
__device__ u64   g_Adup[B_ * H_ * N_];
__device__ float g_Bv  [B_ * H_ * N_];
__device__ float g_P   [B_ * N_];
__device__ float g_Q   [B_ * N_];

// Upper-triangle 64x64 tile list (It <= Jt), 36 tiles per batch.
__constant__ int c_IT[36] = {0,0,0,0,0,0,0,0, 1,1,1,1,1,1,1, 2,2,2,2,2,2,
                             3,3,3,3,3, 4,4,4,4, 5,5,5, 6,6, 7};
__constant__ int c_JT[36] = {0,1,2,3,4,5,6,7, 1,2,3,4,5,6,7, 2,3,4,5,6,7,
                             3,4,5,6,7, 4,5,6,7, 5,6,7, 6,7, 7};

// ---- packed f32x2 helpers (sm_100+) ---------------------------------------
__device__ __forceinline__ u64 f32x2_add(u64 a, u64 b) {
    u64 r; asm("add.rn.f32x2 %0, %1, %2;" : "=l"(r) : "l"(a), "l"(b)); return r;
}
__device__ __forceinline__ u64 f32x2_fma(u64 a, u64 b, u64 c) {
    u64 r; asm("fma.rn.f32x2 %0, %1, %2, %3;" : "=l"(r) : "l"(a), "l"(b), "l"(c)); return r;
}
#define ABS2_MASK 0x7FFFFFFF7FFFFFFFULL

// ---------------------------------------------------------------------------
// Kernel 1: x^T @ [W1a | W1b] -> g_Adup (dup pairs, b1 folded), g_Bv.
// grid (N/256, 16, B), 256 threads; thread owns one n, 16 hu's.
// ---------------------------------------------------------------------------
__global__ void __launch_bounds__(256) precompute_AB(
        const float* __restrict__ x,
        const float* __restrict__ W1,
        const float* __restrict__ b1) {
    __shared__ float Wsh[C_ * 16];  // [c][k]

    const int tid = threadIdx.x;
    const int n   = blockIdx.x * 256 + tid;
    const int hu0 = blockIdx.y * 16;
    const int b   = blockIdx.z;

    #pragma unroll
    for (int r = 0; r < 4; r++) {
        int idx = tid + 256 * r;          // 0..1023
        int c = idx >> 4;
        int k = idx & 15;
        int hu = hu0 + k;
        Wsh[idx] = (hu < H_) ? W1[c * H_ + hu]
                             : W1[(C_ + c) * H_ + (hu - H_)];
    }
    __syncthreads();

    float acc[16];
    #pragma unroll
    for (int k = 0; k < 16; k++) acc[k] = 0.0f;

    const float* xp = x + (b * C_) * N_ + n;
    #pragma unroll 4
    for (int c = 0; c < C_; c++) {
        float xv = xp[c * N_];
        const float4* w4 = (const float4*)(Wsh + c * 16);
        float4 w0 = w4[0], w1 = w4[1], w2 = w4[2], w3 = w4[3];
        acc[0]  = fmaf(xv, w0.x, acc[0]);  acc[1]  = fmaf(xv, w0.y, acc[1]);
        acc[2]  = fmaf(xv, w0.z, acc[2]);  acc[3]  = fmaf(xv, w0.w, acc[3]);
        acc[4]  = fmaf(xv, w1.x, acc[4]);  acc[5]  = fmaf(xv, w1.y, acc[5]);
        acc[6]  = fmaf(xv, w1.z, acc[6]);  acc[7]  = fmaf(xv, w1.w, acc[7]);
        acc[8]  = fmaf(xv, w2.x, acc[8]);  acc[9]  = fmaf(xv, w2.y, acc[9]);
        acc[10] = fmaf(xv, w2.z, acc[10]); acc[11] = fmaf(xv, w2.w, acc[11]);
        acc[12] = fmaf(xv, w3.x, acc[12]); acc[13] = fmaf(xv, w3.y, acc[13]);
        acc[14] = fmaf(xv, w3.z, acc[14]); acc[15] = fmaf(xv, w3.w, acc[15]);
    }

    if (hu0 < H_) {
        #pragma unroll
        for (int k = 0; k < 16; k++) {
            int h = hu0 + k;
            u64 a = (u64)__float_as_uint(acc[k] + b1[h]);
            g_Adup[((b * H_) + h) * N_ + n] = a | (a << 32);
        }
    } else {
        #pragma unroll
        for (int k = 0; k < 16; k++) {
            int h = hu0 + k - H_;
            g_Bv[((b * H_) + h) * N_ + n] = acc[k];
        }
    }
}

// ---------------------------------------------------------------------------
// Kernel 1b: rank-1 linear terms. grid (B, N/128), 128 threads.
//   P[b][n] = b2 + sum_h w'_h * A[b][h][n],  Q[b][n] = sum_h w'_h * Bv[b][h][n]
// ---------------------------------------------------------------------------
__global__ void __launch_bounds__(128) precompute_PQ(
        const float* __restrict__ W2,
        const float* __restrict__ b2) {
    __shared__ float Wsh[H_];
    const int tid = threadIdx.x;
    const int b   = blockIdx.x;
    const int n   = blockIdx.y * 128 + tid;

    Wsh[tid] = 0.5f * W2[tid];
    __syncthreads();

    const float* Af = (const float*)g_Adup;  // low word of dup pair at index 2*idx
    float P = b2[0], Q = 0.f;
    #pragma unroll 8
    for (int h = 0; h < H_; h++) {
        int idx = ((b * H_) + h) * N_ + n;
        float w = Wsh[h];
        P = fmaf(w, Af[2 * idx], P);
        Q = fmaf(w, g_Bv[idx],   Q);
    }
    g_P[b * N_ + n] = P;
    g_Q[b * N_ + n] = Q;
}

// ---------------------------------------------------------------------------
// Kernel 2: for upper-triangle 64x64 tiles only:
//   y[b,i,j] = P_i + Q_j + sum_h w'_h |A_ih + B_jh|   (relu(u) = (u+|u|)/2)
// grid (36, B), 256 threads, 4i x 4j per thread (2 packed j-pairs).
// ---------------------------------------------------------------------------
__global__ void __launch_bounds__(256) pairwise_score(float* __restrict__ out) {
    const int t   = blockIdx.x;
    const int b   = blockIdx.y;
    const int It  = c_IT[t];
    const int Jt  = c_JT[t];
    const int tid = threadIdx.x;
    float* outb = out + b * N_ * N_;

    __shared__ u64   Adup[64 * 64];  // [hh][ii] dup pairs (32 KB)
    __shared__ float Bsh[64 * 64];   // [hh][jj]           (16 KB)
    __shared__ u64   Wsh2[H_];       // (w/2, w/2)
    __shared__ float Psh[64];
    __shared__ float Qsh[64];

    // One-time staging of W2 / P / Q
    {
        const float* W2h = (const float*)0;  // unused placeholder removed below
        (void)W2h;
    }
    if (tid < H_) {
        // w' already halved in k1b? No — k1b halves only its local copy. Halve here too.
        // W2 is not passed; derive w' from g_P/g_Q? No — pass via global const: we
        // instead recompute from the weight input. (W2 passed as kernel arg below.)
    }
    // (actual staging happens in the parameterized section below)

    // --- the above placeholders are resolved by passing W2 as an argument ---
    // (see launcher) -- this block intentionally left minimal.
    extern __shared__ int _dummy[];  // no dynamic smem used
    (void)_dummy;

    // NOTE: W2 pointer comes through a __device__ global set below.
    // (Removed; see pairwise_score2.)
    if (tid == 0x7FFFFFFF) outb[0] = 0.f;  // never executes
}

// Clean implementation with W2 as a parameter.
__global__ void __launch_bounds__(256) pairwise_score2(
        const float* __restrict__ W2,
        float* __restrict__ out) {
    const int t   = blockIdx.x;
    const int b   = blockIdx.y;
    const int It  = c_IT[t];
    const int Jt  = c_JT[t];
    const int tid = threadIdx.x;
    float* outb = out + b * N_ * N_;

    __shared__ u64   Adup[64 * 64];  // [hh][ii] dup pairs (32 KB)
    __shared__ float Bsh[64 * 64];   // [hh][jj]           (16 KB)
    __shared__ u64   Wsh2[H_];       // (w/2, w/2)
    __shared__ float Psh[64];
    __shared__ float Qsh[64];

    if (tid < H_) {
        u64 w = (u64)__float_as_uint(0.5f * W2[tid]);
        Wsh2[tid] = w | (w << 32);
    }
    if (tid < 64)       Psh[tid]      = g_P[b * N_ + It * 64 + tid];
    else if (tid < 128) Qsh[tid - 64] = g_Q[b * N_ + Jt * 64 + (tid - 64)];

    const int ti  = tid >> 4;     // 0..15 -> i-local = 4*ti
    const int tj  = tid & 15;     // 0..15 -> j-local = 4*tj
    const int il0 = ti * 4;
    const int jl0 = tj * 4;

    u64 acc[4][2];
    #pragma unroll
    for (int p = 0; p < 4; p++) { acc[p][0] = 0ULL; acc[p][1] = 0ULL; }

    #pragma unroll
    for (int hb = 0; hb < 2; hb++) {
        __syncthreads();
        const u64*   Ag = g_Adup + (size_t)((b * H_) + hb * 64) * N_ + It * 64;
        const float* Bg = g_Bv   + (size_t)((b * H_) + hb * 64) * N_ + Jt * 64;

        // Stage A: 64hh x 64ii u64 = 2048 float4 -> 8 per thread (straight copy)
        #pragma unroll
        for (int r = 0; r < 8; r++) {
            int l  = tid + 256 * r;     // float4 index 0..2047
            int hh = l >> 5;            // 32 float4 per row
            int c4 = l & 31;
            ((float4*)(Adup + hh * 64))[c4] =
                ((const float4*)(Ag + (size_t)hh * N_))[c4];
        }
        // Stage B: 64hh x 64jj f32 = 1024 float4 -> 4 per thread
        #pragma unroll
        for (int r = 0; r < 4; r++) {
            int l  = tid + 256 * r;     // float4 index 0..1023
            int hh = l >> 4;
            int c4 = l & 15;
            ((float4*)(Bsh + hh * 64))[c4] =
                ((const float4*)(Bg + (size_t)hh * N_))[c4];
        }
        __syncthreads();

        const u64*   Ap = Adup + il0;
        const float* Bp = Bsh + jl0;
        const u64*   Wp = Wsh2 + hb * 64;
        #pragma unroll 4
        for (int hh = 0; hh < 64; hh++) {
            u64 w2 = Wp[hh];
            ulonglong2 a01 = *(const ulonglong2*)(Ap + hh * 64);
            ulonglong2 a23 = *(const ulonglong2*)(Ap + hh * 64 + 2);
            ulonglong2 bb  = *(const ulonglong2*)(Bp + hh * 64);
            u64 av[4] = {a01.x, a01.y, a23.x, a23.y};
            u64 u;
            #pragma unroll
            for (int p = 0; p < 4; p++) {
                u = f32x2_add(av[p], bb.x) & ABS2_MASK;
                acc[p][0] = f32x2_fma(u, w2, acc[p][0]);
                u = f32x2_add(av[p], bb.y) & ABS2_MASK;
                acc[p][1] = f32x2_fma(u, w2, acc[p][1]);
            }
        }
    }
    __syncthreads();  // protect Psh/Qsh reads (already written pre-loop; harmless)

    const int i0 = It * 64 + il0;
    const int j0 = Jt * 64 + jl0;
    const bool diag = (It == Jt);

    float q0 = Qsh[jl0], q1 = Qsh[jl0 + 1], q2 = Qsh[jl0 + 2], q3 = Qsh[jl0 + 3];
    #pragma unroll
    for (int p = 0; p < 4; p++) {
        int i = i0 + p;
        float pb = Psh[il0 + p];
        float4 v;
        v.x = pb + q0 + __uint_as_float((unsigned)(acc[p][0]));
        v.y = pb + q1 + __uint_as_float((unsigned)(acc[p][0] >> 32));
        v.z = pb + q2 + __uint_as_float((unsigned)(acc[p][1]));
        v.w = pb + q3 + __uint_as_float((unsigned)(acc[p][1] >> 32));
        if (diag) {   // strict upper-triangle mask j > i
            if (!(j0 + 0 > i)) v.x = 0.f;
            if (!(j0 + 1 > i)) v.y = 0.f;
            if (!(j0 + 2 > i)) v.z = 0.f;
            if (!(j0 + 3 > i)) v.w = 0.f;
        }
        *(float4*)(outb + i * N_ + j0) = v;
    }
}

// ---------------------------------------------------------------------------
// Inputs: 0:x (B,C,N) f32, 1:W1 (2C,H) f32, 2:b1 (H) f32, 3:W2 (H,1) f32,
//         4:b2 (1) f32.  Output: (B,N,N) f32.
// ---------------------------------------------------------------------------
extern "C" void kernel_launch(void* const* d_in, const int* in_sizes, int n_in,
                              void* d_out, int out_size) {
    const float* x  = (const float*)d_in[0];
    const float* W1 = (const float*)d_in[1];
    const float* b1 = (const float*)d_in[2];
    const float* W2 = (const float*)d_in[3];
    const float* b2 = (const float*)d_in[4];
    float* out = (float*)d_out;

    // Zero the full output (lower triangle + diagonal baseline).
    cudaMemsetAsync(out, 0, (size_t)out_size * sizeof(float));

    dim3 g1(N_ / 256, (2 * H_) / 16, B_);   // (2, 16, 4)
    precompute_AB<<<g1, 256>>>(x, W1, b1);

    dim3 g1b(B_, N_ / 128);                 // (4, 4)
    precompute_PQ<<<g1b, 128>>>(W2, b2);

    dim3 g2(36, B_);                        // 144 compute tiles, one wave
    pairwise_score2<<<g2, 256>>>(W2, out);
}

// round 4
// speedup vs baseline: 1.8548x; 1.8548x over previous
#include <cuda_runtime.h>

// Problem constants: B=4, C=64, N=512, H=128, 2C=128.
#define B_ 4
#define C_ 64
#define N_ 512
#define H_ 128

typedef unsigned long long u64;

// Scratch (h-major, plain f32):
//   g_A [b][h][n] = b1[h] + sum_c x[b,c,n]*W1[c][h]
//   g_Bv[b][h][n] =         sum_c x[b,c,n]*W1[C+c][h]
//   g_PQp[gy][b][n]: gy 0..3 = P partials (32-h chunks), gy 4..7 = Q partials,
//   with P = sum_h (W2[h]/2)*A, Q = sum_h (W2[h]/2)*Bv. Written exactly once.
__device__ float g_A  [B_ * H_ * N_];
__device__ float g_Bv [B_ * H_ * N_];
__device__ float g_PQp[8 * B_ * N_];

// Upper-triangle (It<=Jt, 36) and strict-lower (It>Jt, 28) 64x64 tile lists.
__constant__ int c_IT[36] = {0,0,0,0,0,0,0,0, 1,1,1,1,1,1,1, 2,2,2,2,2,2,
                             3,3,3,3,3, 4,4,4,4, 5,5,5, 6,6, 7};
__constant__ int c_JT[36] = {0,1,2,3,4,5,6,7, 1,2,3,4,5,6,7, 2,3,4,5,6,7,
                             3,4,5,6,7, 4,5,6,7, 5,6,7, 6,7, 7};
__constant__ int c_LI[28] = {1, 2,2, 3,3,3, 4,4,4,4, 5,5,5,5,5,
                             6,6,6,6,6,6, 7,7,7,7,7,7,7};
__constant__ int c_LJ[28] = {0, 0,1, 0,1,2, 0,1,2,3, 0,1,2,3,4,
                             0,1,2,3,4,5, 0,1,2,3,4,5,6};

// ---- packed f32x2 helpers (sm_100+) ---------------------------------------
__device__ __forceinline__ u64 f32x2_add(u64 a, u64 b) {
    u64 r; asm("add.rn.f32x2 %0, %1, %2;" : "=l"(r) : "l"(a), "l"(b)); return r;
}
__device__ __forceinline__ u64 f32x2_fma(u64 a, u64 b, u64 c) {
    u64 r; asm("fma.rn.f32x2 %0, %1, %2, %3;" : "=l"(r) : "l"(a), "l"(b), "l"(c)); return r;
}
__device__ __forceinline__ u64 dup32(float x) {
    u64 r; asm("mov.b64 %0, {%1, %1};" : "=l"(r) : "f"(x)); return r;
}
__device__ __forceinline__ u64 swap32(u64 v) {
    u64 r;
    asm("{\n\t.reg .b32 lo, hi;\n\tmov.b64 {lo, hi}, %1;\n\tmov.b64 %0, {hi, lo};\n\t}"
        : "=l"(r) : "l"(v));
    return r;
}
__device__ __forceinline__ float lo32(u64 v) { return __uint_as_float((unsigned)v); }
__device__ __forceinline__ float hi32(u64 v) { return __uint_as_float((unsigned)(v >> 32)); }
#define ABS2_MASK 0x7FFFFFFF7FFFFFFFULL

// ---------------------------------------------------------------------------
// Kernel 1: shared-staged GEMM  x^T @ [W1a | W1b] -> g_A (b1 folded), g_Bv,
// plus per-chunk P/Q partials into g_PQp.
// grid (N/128=4, 8 hu-chunks of 32, B), block 256. Thread: 2 n x 8 hu (f32x2).
// ---------------------------------------------------------------------------
__global__ void __launch_bounds__(256) precompute_AB(
        const float* __restrict__ x,
        const float* __restrict__ W1,
        const float* __restrict__ b1,
        const float* __restrict__ W2) {
    __shared__ float xs[C_ * 128];     // [c][n_loc]  32 KB
    __shared__ float ws[C_ * 32];      // [c][k]       8 KB
    __shared__ float w2s[32];
    __shared__ float b1s[32];
    __shared__ float sPart[4 * 128];   // [hgroup][n_loc] 2 KB

    const int tid = threadIdx.x;
    const int n0  = blockIdx.x * 128;
    const int gy  = blockIdx.y;        // 0..7
    const int b   = blockIdx.z;
    const bool isA = (gy < 4);
    const int h0   = (isA ? gy : gy - 4) * 32;   // output h base 0..96
    const int crow = isA ? 0 : C_;               // W1 row offset

    // Stage x tile: 64c x 128n = 2048 float4, 8 per thread.
    const float* xb = x + (size_t)(b * C_) * N_ + n0;
    #pragma unroll
    for (int r = 0; r < 8; r++) {
        int idx = tid + 256 * r;
        int c   = idx >> 5;
        int n4  = idx & 31;
        ((float4*)(xs + c * 128))[n4] = ((const float4*)(xb + (size_t)c * N_))[n4];
    }
    // Stage W slice: 64c x 32hu = 512 float4, 2 per thread.
    #pragma unroll
    for (int r = 0; r < 2; r++) {
        int idx = tid + 256 * r;
        int c   = idx >> 3;
        int k4  = idx & 7;
        ((float4*)(ws + c * 32))[k4] =
            ((const float4*)(W1 + (size_t)(crow + c) * H_ + h0))[k4];
    }
    if (tid < 32) {
        w2s[tid] = 0.5f * W2[h0 + tid];
        b1s[tid] = isA ? b1[h0 + tid] : 0.0f;
    }
    __syncthreads();

    const int nl0 = (tid & 63) * 2;
    const int hl0 = (tid >> 6) * 8;

    u64 acc[2][4];
    #pragma unroll
    for (int p = 0; p < 2; p++)
        #pragma unroll
        for (int k = 0; k < 4; k++) acc[p][k] = 0ULL;

    #pragma unroll 8
    for (int c = 0; c < C_; c++) {
        float2 xv = *(const float2*)(xs + c * 128 + nl0);
        u64 x0 = dup32(xv.x);
        u64 x1 = dup32(xv.y);
        const ulonglong2* wp = (const ulonglong2*)(ws + c * 32 + hl0);
        ulonglong2 w01 = wp[0];
        ulonglong2 w23 = wp[1];
        acc[0][0] = f32x2_fma(x0, w01.x, acc[0][0]);
        acc[0][1] = f32x2_fma(x0, w01.y, acc[0][1]);
        acc[0][2] = f32x2_fma(x0, w23.x, acc[0][2]);
        acc[0][3] = f32x2_fma(x0, w23.y, acc[0][3]);
        acc[1][0] = f32x2_fma(x1, w01.x, acc[1][0]);
        acc[1][1] = f32x2_fma(x1, w01.y, acc[1][1]);
        acc[1][2] = f32x2_fma(x1, w23.x, acc[1][2]);
        acc[1][3] = f32x2_fma(x1, w23.y, acc[1][3]);
    }

    // Epilogue: add b1, store float2 (n, n+1) per h, accumulate P/Q partials.
    float* outb = (isA ? g_A : g_Bv) + (size_t)(b * H_ + h0) * N_ + n0 + nl0;
    float p0 = 0.f, p1 = 0.f;
    #pragma unroll
    for (int k = 0; k < 4; k++) {
        #pragma unroll
        for (int s = 0; s < 2; s++) {
            int hl = hl0 + 2 * k + s;
            float bias = b1s[hl];
            float a0 = (s ? hi32(acc[0][k]) : lo32(acc[0][k])) + bias;
            float a1 = (s ? hi32(acc[1][k]) : lo32(acc[1][k])) + bias;
            *(float2*)(outb + (size_t)hl * N_) = make_float2(a0, a1);
            float w = w2s[hl];
            p0 = fmaf(w, a0, p0);
            p1 = fmaf(w, a1, p1);
        }
    }
    sPart[(tid >> 6) * 128 + nl0]     = p0;
    sPart[(tid >> 6) * 128 + nl0 + 1] = p1;
    __syncthreads();
    if (tid < 128) {
        float s = sPart[tid] + sPart[128 + tid] + sPart[256 + tid] + sPart[384 + tid];
        g_PQp[gy * (B_ * N_) + b * N_ + n0 + tid] = s;
    }
}

// ---------------------------------------------------------------------------
// Kernel 2: 256 blocks (1D), 256 threads.
//   bid < 144: compute tile t=bid>>2, b=bid&3 (upper-tri 64x64):
//     y[i,j] = P_i + b2 + Q_j + sum_h w'_h |A_ih + B_jh|
//   bid >= 144: strict-lower tile zero-fill.
// Thread: 4i x 4j via f32x2 pairs + word-rotation (no duplicated operands).
// ---------------------------------------------------------------------------
__global__ void __launch_bounds__(256) pairwise_score(
        const float* __restrict__ W2,
        const float* __restrict__ b2,
        float* __restrict__ out) {
    const int t   = blockIdx.x;
    const int tid = threadIdx.x;

    if (t >= 144) {   // zero-fill strict-lower tiles
        int z  = t - 144;
        int b  = z & 3;
        int zt = z >> 2;
        float* outb = out + (size_t)b * N_ * N_ + (size_t)(c_LI[zt] * 64) * N_ + c_LJ[zt] * 64;
        const float4 zf = make_float4(0.f, 0.f, 0.f, 0.f);
        #pragma unroll
        for (int r = 0; r < 4; r++) {
            int l  = tid + 256 * r;   // float4 index 0..1023
            int ii = l >> 4;
            int j4 = l & 15;
            ((float4*)(outb + (size_t)ii * N_))[j4] = zf;
        }
        return;
    }

    const int b  = t & 3;
    const int tl = t >> 2;
    const int It = c_IT[tl];
    const int Jt = c_JT[tl];
    float* outb = out + (size_t)b * N_ * N_;

    __shared__ float Ash[64 * 64];   // [hh][ii] 16 KB
    __shared__ float Bsh[64 * 64];   // [hh][jj] 16 KB
    __shared__ u64   Wsh2[H_];       // (w/2, w/2) dup
    __shared__ float Psh[64];        // includes b2
    __shared__ float Qsh[64];

    if (tid < H_) {
        u64 w = (u64)__float_as_uint(0.5f * W2[tid]);
        Wsh2[tid] = w | (w << 32);
    }
    if (tid < 64) {
        int n = It * 64 + tid;
        Psh[tid] = g_PQp[0 * B_ * N_ + b * N_ + n] + g_PQp[1 * B_ * N_ + b * N_ + n]
                 + g_PQp[2 * B_ * N_ + b * N_ + n] + g_PQp[3 * B_ * N_ + b * N_ + n]
                 + b2[0];
    } else if (tid < 128) {
        int n = Jt * 64 + (tid - 64);
        Qsh[tid - 64] = g_PQp[4 * B_ * N_ + b * N_ + n] + g_PQp[5 * B_ * N_ + b * N_ + n]
                      + g_PQp[6 * B_ * N_ + b * N_ + n] + g_PQp[7 * B_ * N_ + b * N_ + n];
    }

    const int il0 = (tid >> 4) * 4;
    const int jl0 = (tid & 15) * 4;

    u64 a00 = 0, a00r = 0, a01 = 0, a01r = 0;
    u64 a10 = 0, a10r = 0, a11 = 0, a11r = 0;

    #pragma unroll
    for (int hb = 0; hb < 2; hb++) {
        __syncthreads();
        const float* Ag = g_A  + (size_t)(b * H_ + hb * 64) * N_ + It * 64;
        const float* Bg = g_Bv + (size_t)(b * H_ + hb * 64) * N_ + Jt * 64;
        #pragma unroll
        for (int r = 0; r < 4; r++) {
            int l  = tid + 256 * r;   // float4 index 0..1023
            int hh = l >> 4;
            int c4 = l & 15;
            ((float4*)(Ash + hh * 64))[c4] = ((const float4*)(Ag + (size_t)hh * N_))[c4];
            ((float4*)(Bsh + hh * 64))[c4] = ((const float4*)(Bg + (size_t)hh * N_))[c4];
        }
        __syncthreads();

        const float* Ap = Ash + il0;
        const float* Bp = Bsh + jl0;
        const u64*   Wp = Wsh2 + hb * 64;
        #pragma unroll 4
        for (int hh = 0; hh < 64; hh++) {
            u64 w2 = Wp[hh];
            ulonglong2 aa = *(const ulonglong2*)(Ap + hh * 64);  // (a0,a1),(a2,a3)
            ulonglong2 bb = *(const ulonglong2*)(Bp + hh * 64);  // (b0,b1),(b2,b3)
            u64 b0r = swap32(bb.x);                              // (b1,b0)
            u64 b1r = swap32(bb.y);                              // (b3,b2)
            u64 u;
            u = f32x2_add(aa.x, bb.x) & ABS2_MASK; a00  = f32x2_fma(u, w2, a00);
            u = f32x2_add(aa.x, b0r ) & ABS2_MASK; a00r = f32x2_fma(u, w2, a00r);
            u = f32x2_add(aa.x, bb.y) & ABS2_MASK; a01  = f32x2_fma(u, w2, a01);
            u = f32x2_add(aa.x, b1r ) & ABS2_MASK; a01r = f32x2_fma(u, w2, a01r);
            u = f32x2_add(aa.y, bb.x) & ABS2_MASK; a10  = f32x2_fma(u, w2, a10);
            u = f32x2_add(aa.y, b0r ) & ABS2_MASK; a10r = f32x2_fma(u, w2, a10r);
            u = f32x2_add(aa.y, bb.y) & ABS2_MASK; a11  = f32x2_fma(u, w2, a11);
            u = f32x2_add(aa.y, b1r ) & ABS2_MASK; a11r = f32x2_fma(u, w2, a11r);
        }
    }

    // Epilogue. Lane mapping:
    //  row il0+0: [lo a00, lo a00r, lo a01, lo a01r]
    //  row il0+1: [hi a00r, hi a00, hi a01r, hi a01]
    //  row il0+2: [lo a10, lo a10r, lo a11, lo a11r]
    //  row il0+3: [hi a10r, hi a10, hi a11r, hi a11]
    float rv[4][4];
    rv[0][0] = lo32(a00);  rv[0][1] = lo32(a00r); rv[0][2] = lo32(a01);  rv[0][3] = lo32(a01r);
    rv[1][0] = hi32(a00r); rv[1][1] = hi32(a00);  rv[1][2] = hi32(a01r); rv[1][3] = hi32(a01);
    rv[2][0] = lo32(a10);  rv[2][1] = lo32(a10r); rv[2][2] = lo32(a11);  rv[2][3] = lo32(a11r);
    rv[3][0] = hi32(a10r); rv[3][1] = hi32(a10);  rv[3][2] = hi32(a11r); rv[3][3] = hi32(a11);

    const int i0 = It * 64 + il0;
    const int j0 = Jt * 64 + jl0;
    const bool diag = (It == Jt);

    float q0 = Qsh[jl0], q1 = Qsh[jl0 + 1], q2 = Qsh[jl0 + 2], q3 = Qsh[jl0 + 3];
    #pragma unroll
    for (int r = 0; r < 4; r++) {
        int i = i0 + r;
        float pb = Psh[il0 + r];
        float4 v;
        v.x = pb + q0 + rv[r][0];
        v.y = pb + q1 + rv[r][1];
        v.z = pb + q2 + rv[r][2];
        v.w = pb + q3 + rv[r][3];
        if (diag) {   // strict upper-triangle mask j > i
            if (!(j0 + 0 > i)) v.x = 0.f;
            if (!(j0 + 1 > i)) v.y = 0.f;
            if (!(j0 + 2 > i)) v.z = 0.f;
            if (!(j0 + 3 > i)) v.w = 0.f;
        }
        *(float4*)(outb + (size_t)i * N_ + j0) = v;
    }
}

// ---------------------------------------------------------------------------
// Inputs: 0:x (B,C,N) f32, 1:W1 (2C,H) f32, 2:b1 (H) f32, 3:W2 (H,1) f32,
//         4:b2 (1) f32.  Output: (B,N,N) f32.
// ---------------------------------------------------------------------------
extern "C" void kernel_launch(void* const* d_in, const int* in_sizes, int n_in,
                              void* d_out, int out_size) {
    const float* x  = (const float*)d_in[0];
    const float* W1 = (const float*)d_in[1];
    const float* b1 = (const float*)d_in[2];
    const float* W2 = (const float*)d_in[3];
    const float* b2 = (const float*)d_in[4];
    float* out = (float*)d_out;

    dim3 g1(N_ / 128, 8, B_);     // (4, 8, 4) = 128 blocks
    precompute_AB<<<g1, 256>>>(x, W1, b1, W2);

    pairwise_score<<<256, 256>>>(W2, b2, out);   // 144 compute + 112 zero-fill
}